// round 12
// baseline (speedup 1.0000x reference)
#include <cuda_runtime.h>
#include <cuda_fp16.h>
#include <cstdint>

// Problem dims
#define BATCH 8
#define SEQ   2048
#define KDIM  4096
#define MDIM  4096
#define NDIM  (BATCH * SEQ)   // 16384

// GEMM tiling: CTA 128x128x64, 4 warps (2m x 2n), warp tile 64x64; 2 CTAs/SM
#define BM 128
#define BN 128
#define BK 64
#define NST 3
#define GTHREADS 128
#define KITERS (KDIM / BK)    // 64

#define A_BYTES (BM * 128)                 // 16384
#define B_BYTES (BN * 128)                 // 16384
#define STAGE_BYTES (A_BYTES + B_BYTES)    // 32768
#define SMEM_TOTAL (NST * STAGE_BYTES)     // 98304 -> 2 CTAs per SM

// fp16 scratch
__device__ __align__(16) __half g_Wh[(size_t)MDIM * KDIM];   // 32 MB
__device__ __align__(16) __half g_Xh[(size_t)NDIM * KDIM];   // 128 MB

// ---------------------------------------------------------------------------
// Fused conversion kernel: blocks [0, 2048) -> W*mask, [2048, 10240) -> X
// ---------------------------------------------------------------------------
__global__ void convert_all(const float* __restrict__ x,
                            const float* __restrict__ w,
                            const int* __restrict__ mask) {
    if (blockIdx.x < 2048) {
        size_t total4 = (size_t)MDIM * KDIM / 4;
        for (size_t i = (size_t)blockIdx.x * blockDim.x + threadIdx.x;
             i < total4; i += (size_t)2048 * blockDim.x) {
            float4 wv = reinterpret_cast<const float4*>(w)[i];
            int4   mv = reinterpret_cast<const int4*>(mask)[i];
            float a = mv.x ? wv.x : 0.0f;
            float b = mv.y ? wv.y : 0.0f;
            float c = mv.z ? wv.z : 0.0f;
            float d = mv.w ? wv.w : 0.0f;
            __half2* o = reinterpret_cast<__half2*>(&g_Wh[i * 4]);
            o[0] = __floats2half2_rn(a, b);
            o[1] = __floats2half2_rn(c, d);
        }
    } else {
        size_t total4 = (size_t)NDIM * KDIM / 4;
        for (size_t i = (size_t)(blockIdx.x - 2048) * blockDim.x + threadIdx.x;
             i < total4; i += (size_t)8192 * blockDim.x) {
            float4 xv = reinterpret_cast<const float4*>(x)[i];
            __half2* o = reinterpret_cast<__half2*>(&g_Xh[i * 4]);
            o[0] = __floats2half2_rn(xv.x, xv.y);
            o[1] = __floats2half2_rn(xv.z, xv.w);
        }
    }
}

// ---------------------------------------------------------------------------
// Helpers
// ---------------------------------------------------------------------------
__device__ __forceinline__ uint32_t smem_u32(const void* p) {
    uint32_t a;
    asm("{ .reg .u64 t; cvta.to.shared.u64 t, %1; cvt.u32.u64 %0, t; }"
        : "=r"(a) : "l"(p));
    return a;
}

__device__ __forceinline__ void ldsm_x4(uint32_t& r0, uint32_t& r1,
                                        uint32_t& r2, uint32_t& r3,
                                        uint32_t addr) {
    asm volatile("ldmatrix.sync.aligned.m8n8.x4.shared.b16 {%0,%1,%2,%3}, [%4];"
                 : "=r"(r0), "=r"(r1), "=r"(r2), "=r"(r3) : "r"(addr));
}

__device__ __forceinline__ void mma16816(float* c, const uint32_t* a,
                                         uint32_t b0, uint32_t b1) {
    asm volatile(
        "mma.sync.aligned.m16n8k16.row.col.f32.f16.f16.f32 "
        "{%0,%1,%2,%3}, {%4,%5,%6,%7}, {%8,%9}, {%0,%1,%2,%3};"
        : "+f"(c[0]), "+f"(c[1]), "+f"(c[2]), "+f"(c[3])
        : "r"(a[0]), "r"(a[1]), "r"(a[2]), "r"(a[3]), "r"(b0), "r"(b1));
}

// ---------------------------------------------------------------------------
// Producer: 2048 x 16B cp.async per stage (A 1024, B 1024), 16 per thread.
// ---------------------------------------------------------------------------
__device__ __forceinline__ void produce(uint32_t stage, int tid, int j,
                                        int mBase, int nBase) {
    const __half* aseg = &g_Wh[(size_t)mBase * KDIM + j * BK];
    const __half* bseg = &g_Xh[(size_t)nBase * KDIM + j * BK];
#pragma unroll
    for (int t = 0; t < 16; t++) {
        int id = tid + t * GTHREADS;          // 0..2047
        int isB = (id >= 1024);
        int lid = id & 1023;
        int row = lid >> 3;
        int c   = lid & 7;
        const __half* src = (isB ? bseg : aseg) + (size_t)row * KDIM + c * 8;
        uint32_t off = row * 128 + c * 16;
        uint32_t dst = stage + (isB ? A_BYTES : 0) + (off ^ ((off >> 3) & 0x70));
        asm volatile("cp.async.cg.shared.global [%0], [%1], 16;"
                     :: "r"(dst), "l"(src) : "memory");
    }
}

// ---------------------------------------------------------------------------
// GEMM: C[m,n] = sum_k Wh[m,k] * Xh[n,k]
// 4 warps, warp tile 64x64: operand duplication 2+2 -> 375 B/mma < crossbar budget
// ---------------------------------------------------------------------------
__global__ void __launch_bounds__(GTHREADS, 2)
gemm_hmma(float* __restrict__ out) {
    extern __shared__ __align__(1024) char smem[];
    const uint32_t sb = smem_u32(smem);
    const int tid = threadIdx.x;
    const int lane = tid & 31;
    const int wid = tid >> 5;
    const int wm = wid >> 1;          // 0..1  (m offset wm*64)
    const int wn = wid & 1;           // 0..1  (n offset wn*64)

    const int mBase = blockIdx.x * BM;
    const int nBase = blockIdx.y * BN;

    // Per-lane ldmatrix offsets
    const int aRow = wm * 64 + (lane & 15);
    const uint32_t aOff0 = (uint32_t)aRow * 128 + ((lane >> 4) << 4);
    const uint32_t aMask = ((((uint32_t)aRow * 128) >> 3) & 0x70);
    const int bRow = wn * 64 + (lane & 7) + ((lane >> 4) << 3);
    const uint32_t bOff0 = (uint32_t)bRow * 128 + (((lane >> 3) & 1) << 4);
    const uint32_t bMask = ((((uint32_t)bRow * 128) >> 3) & 0x70);

    float acc[4][8][4];               // 4 m16 x 8 n8 = 128 regs
#pragma unroll
    for (int i = 0; i < 4; i++)
#pragma unroll
        for (int j = 0; j < 8; j++)
#pragma unroll
            for (int r = 0; r < 4; r++) acc[i][j][r] = 0.0f;

    produce(sb + 0 * STAGE_BYTES, tid, 0, mBase, nBase);
    asm volatile("cp.async.commit_group;" ::: "memory");
    produce(sb + 1 * STAGE_BYTES, tid, 1, mBase, nBase);
    asm volatile("cp.async.commit_group;" ::: "memory");

    for (int i = 0; i < KITERS; i++) {
        asm volatile("cp.async.wait_group 1;" ::: "memory");
        __syncthreads();

        if (i + 2 < KITERS)
            produce(sb + ((i + 2) % NST) * STAGE_BYTES, tid, i + 2, mBase, nBase);
        asm volatile("cp.async.commit_group;" ::: "memory");

        const uint32_t stA = sb + (i % NST) * STAGE_BYTES;
        const uint32_t stB = stA + A_BYTES;

#pragma unroll
        for (int kk = 0; kk < 4; kk++) {
            uint32_t a[4][4], b[4][4];
#pragma unroll
            for (int mt = 0; mt < 4; mt++) {
                uint32_t off = aOff0 + (uint32_t)mt * 16 * 128 + kk * 32;
                ldsm_x4(a[mt][0], a[mt][1], a[mt][2], a[mt][3],
                        stA + (off ^ aMask));
            }
#pragma unroll
            for (int nt = 0; nt < 4; nt++) {
                uint32_t off = bOff0 + (uint32_t)nt * 16 * 128 + kk * 32;
                ldsm_x4(b[nt][0], b[nt][1], b[nt][2], b[nt][3],
                        stB + (off ^ bMask));
            }
#pragma unroll
            for (int mt = 0; mt < 4; mt++)
#pragma unroll
                for (int nt = 0; nt < 4; nt++) {
                    mma16816(acc[mt][2 * nt],     a[mt], b[nt][0], b[nt][1]);
                    mma16816(acc[mt][2 * nt + 1], a[mt], b[nt][2], b[nt][3]);
                }
        }
    }

    // Epilogue: direct stores; each 4-lane group writes a full 32B sector.
    const int b2 = nBase / SEQ;
    const int s0 = nBase % SEQ;
    const int mW = mBase + wm * 64;
    const int nW = s0 + wn * 64;
    const int rl = lane >> 2;
    const int cl = (lane & 3) * 2;
#pragma unroll
    for (int mt = 0; mt < 4; mt++) {
#pragma unroll
        for (int j = 0; j < 8; j++) {
            size_t base = ((size_t)b2 * MDIM + mW + mt * 16 + rl) * SEQ + nW + j * 8 + cl;
            *reinterpret_cast<float2*>(&out[base]) =
                make_float2(acc[mt][j][0], acc[mt][j][1]);
            *reinterpret_cast<float2*>(&out[base + 8 * SEQ]) =
                make_float2(acc[mt][j][2], acc[mt][j][3]);
        }
    }
}

// ---------------------------------------------------------------------------
// Launch
// ---------------------------------------------------------------------------
extern "C" void kernel_launch(void* const* d_in, const int* in_sizes, int n_in,
                              void* d_out, int out_size) {
    const float* x    = (const float*)d_in[0];   // [B, S, K]
    const float* w    = (const float*)d_in[1];   // [M, K]
    const int*   mask = (const int*)d_in[2];     // [M, K] bool -> int32
    float* out = (float*)d_out;                  // [B, M, S]

    convert_all<<<10240, 256>>>(x, w, mask);

    cudaFuncSetAttribute(gemm_hmma,
                         cudaFuncAttributeMaxDynamicSharedMemorySize, SMEM_TOTAL);
    dim3 grid(MDIM / BM, NDIM / BN);   // (32, 128): m fastest -> W stays in L2
    gemm_hmma<<<grid, GTHREADS, SMEM_TOTAL>>>(out);
}

// round 13
// speedup vs baseline: 1.0651x; 1.0651x over previous
#include <cuda_runtime.h>
#include <cuda_fp16.h>
#include <cstdint>

// Problem dims
#define BATCH 8
#define SEQ   2048
#define KDIM  4096
#define MDIM  4096
#define NDIM  (BATCH * SEQ)   // 16384

// GEMM tiling: CTA 128x128x64, 8 warps (2m x 4n), warp tile 64x32; 2 CTAs/SM
#define BM 128
#define BN 128
#define BK 64
#define NST 3
#define GTHREADS 256
#define KITERS (KDIM / BK)    // 64

#define A_BYTES (BM * 128)                 // 16384
#define B_BYTES (BN * 128)                 // 16384
#define STAGE_BYTES (A_BYTES + B_BYTES)    // 32768
#define SMEM_TOTAL (NST * STAGE_BYTES)     // 98304 -> 2 CTAs per SM

// fp16 scratch
__device__ __align__(16) __half g_Wh[(size_t)MDIM * KDIM];   // 32 MB
__device__ __align__(16) __half g_Xh[(size_t)NDIM * KDIM];   // 128 MB

// ---------------------------------------------------------------------------
// Fused conversion kernel: blocks [0, 2048) -> W*mask, [2048, 10240) -> X
// ---------------------------------------------------------------------------
__global__ void convert_all(const float* __restrict__ x,
                            const float* __restrict__ w,
                            const int* __restrict__ mask) {
    if (blockIdx.x < 2048) {
        size_t total4 = (size_t)MDIM * KDIM / 4;
        for (size_t i = (size_t)blockIdx.x * blockDim.x + threadIdx.x;
             i < total4; i += (size_t)2048 * blockDim.x) {
            float4 wv = reinterpret_cast<const float4*>(w)[i];
            int4   mv = reinterpret_cast<const int4*>(mask)[i];
            float a = mv.x ? wv.x : 0.0f;
            float b = mv.y ? wv.y : 0.0f;
            float c = mv.z ? wv.z : 0.0f;
            float d = mv.w ? wv.w : 0.0f;
            __half2* o = reinterpret_cast<__half2*>(&g_Wh[i * 4]);
            o[0] = __floats2half2_rn(a, b);
            o[1] = __floats2half2_rn(c, d);
        }
    } else {
        size_t total4 = (size_t)NDIM * KDIM / 4;
        for (size_t i = (size_t)(blockIdx.x - 2048) * blockDim.x + threadIdx.x;
             i < total4; i += (size_t)8192 * blockDim.x) {
            float4 xv = reinterpret_cast<const float4*>(x)[i];
            __half2* o = reinterpret_cast<__half2*>(&g_Xh[i * 4]);
            o[0] = __floats2half2_rn(xv.x, xv.y);
            o[1] = __floats2half2_rn(xv.z, xv.w);
        }
    }
}

// ---------------------------------------------------------------------------
// Helpers
// ---------------------------------------------------------------------------
__device__ __forceinline__ uint32_t smem_u32(const void* p) {
    uint32_t a;
    asm("{ .reg .u64 t; cvta.to.shared.u64 t, %1; cvt.u32.u64 %0, t; }"
        : "=r"(a) : "l"(p));
    return a;
}

__device__ __forceinline__ void ldsm_x4(uint32_t& r0, uint32_t& r1,
                                        uint32_t& r2, uint32_t& r3,
                                        uint32_t addr) {
    asm volatile("ldmatrix.sync.aligned.m8n8.x4.shared.b16 {%0,%1,%2,%3}, [%4];"
                 : "=r"(r0), "=r"(r1), "=r"(r2), "=r"(r3) : "r"(addr));
}

__device__ __forceinline__ void mma16816(float* c, const uint32_t* a,
                                         uint32_t b0, uint32_t b1) {
    asm volatile(
        "mma.sync.aligned.m16n8k16.row.col.f32.f16.f16.f32 "
        "{%0,%1,%2,%3}, {%4,%5,%6,%7}, {%8,%9}, {%0,%1,%2,%3};"
        : "+f"(c[0]), "+f"(c[1]), "+f"(c[2]), "+f"(c[3])
        : "r"(a[0]), "r"(a[1]), "r"(a[2]), "r"(a[3]), "r"(b0), "r"(b1));
}

// ---------------------------------------------------------------------------
// Producer: 2048 x 16B cp.async per stage (A 1024, B 1024), 8 per thread.
// ---------------------------------------------------------------------------
__device__ __forceinline__ void produce(uint32_t stage, int tid, int j,
                                        int mBase, int nBase) {
    const __half* aseg = &g_Wh[(size_t)mBase * KDIM + j * BK];
    const __half* bseg = &g_Xh[(size_t)nBase * KDIM + j * BK];
#pragma unroll
    for (int t = 0; t < 8; t++) {
        int id = tid + t * GTHREADS;          // 0..2047
        int isB = (id >= 1024);
        int lid = id & 1023;
        int row = lid >> 3;
        int c   = lid & 7;
        const __half* src = (isB ? bseg : aseg) + (size_t)row * KDIM + c * 8;
        uint32_t off = row * 128 + c * 16;
        uint32_t dst = stage + (isB ? A_BYTES : 0) + (off ^ ((off >> 3) & 0x70));
        asm volatile("cp.async.cg.shared.global [%0], [%1], 16;"
                     :: "r"(dst), "l"(src) : "memory");
    }
}

// ---------------------------------------------------------------------------
// GEMM: C[m,n] = sum_k Wh[m,k] * Xh[n,k]; 2 CTAs/SM; A-ldsm issued before
// produce so producer issue hides under smem latency.
// ---------------------------------------------------------------------------
__global__ void __launch_bounds__(GTHREADS, 2)
gemm_hmma(float* __restrict__ out) {
    extern __shared__ __align__(1024) char smem[];
    const uint32_t sb = smem_u32(smem);
    const int tid = threadIdx.x;
    const int lane = tid & 31;
    const int wid = tid >> 5;
    const int wm = wid >> 2;          // 0..1  (m offset wm*64)
    const int wn = wid & 3;           // 0..3  (n offset wn*32)

    const int mBase = blockIdx.x * BM;
    const int nBase = blockIdx.y * BN;

    // Per-lane ldmatrix offsets
    const int aRow = wm * 64 + (lane & 15);
    const uint32_t aOff0 = (uint32_t)aRow * 128 + ((lane >> 4) << 4);
    const uint32_t aMask = ((((uint32_t)aRow * 128) >> 3) & 0x70);
    const int bRow = wn * 32 + (lane & 7) + ((lane >> 4) << 3);
    const uint32_t bOff0 = (uint32_t)bRow * 128 + (((lane >> 3) & 1) << 4);
    const uint32_t bMask = ((((uint32_t)bRow * 128) >> 3) & 0x70);

    float acc[4][4][4];               // 4 m16 x 4 n8, 64 regs
#pragma unroll
    for (int i = 0; i < 4; i++)
#pragma unroll
        for (int j = 0; j < 4; j++)
#pragma unroll
            for (int r = 0; r < 4; r++) acc[i][j][r] = 0.0f;

    produce(sb + 0 * STAGE_BYTES, tid, 0, mBase, nBase);
    asm volatile("cp.async.commit_group;" ::: "memory");
    produce(sb + 1 * STAGE_BYTES, tid, 1, mBase, nBase);
    asm volatile("cp.async.commit_group;" ::: "memory");

    for (int i = 0; i < KITERS; i++) {
        asm volatile("cp.async.wait_group 1;" ::: "memory");
        __syncthreads();

        const uint32_t stA = sb + (i % NST) * STAGE_BYTES;
        const uint32_t stB = stA + A_BYTES;

        // kk0 A-fragments FIRST: start the smem pipe before producer issue
        uint32_t a[4][4], b[2][4];
#pragma unroll
        for (int mt = 0; mt < 4; mt++) {
            uint32_t off = aOff0 + (uint32_t)mt * 16 * 128;
            ldsm_x4(a[mt][0], a[mt][1], a[mt][2], a[mt][3], stA + (off ^ aMask));
        }

        // Producer issues while A-ldsm is in flight
        if (i + 2 < KITERS)
            produce(sb + ((i + 2) % NST) * STAGE_BYTES, tid, i + 2, mBase, nBase);
        asm volatile("cp.async.commit_group;" ::: "memory");

        // kk0 B-fragments + MMAs
#pragma unroll
        for (int nt = 0; nt < 2; nt++) {
            uint32_t off = bOff0 + (uint32_t)nt * 16 * 128;
            ldsm_x4(b[nt][0], b[nt][1], b[nt][2], b[nt][3], stB + (off ^ bMask));
        }
#pragma unroll
        for (int mt = 0; mt < 4; mt++)
#pragma unroll
            for (int nt = 0; nt < 2; nt++) {
                mma16816(acc[mt][2 * nt],     a[mt], b[nt][0], b[nt][1]);
                mma16816(acc[mt][2 * nt + 1], a[mt], b[nt][2], b[nt][3]);
            }

        // kk = 1..3
#pragma unroll
        for (int kk = 1; kk < 4; kk++) {
#pragma unroll
            for (int mt = 0; mt < 4; mt++) {
                uint32_t off = aOff0 + (uint32_t)mt * 16 * 128 + kk * 32;
                ldsm_x4(a[mt][0], a[mt][1], a[mt][2], a[mt][3],
                        stA + (off ^ aMask));
            }
#pragma unroll
            for (int nt = 0; nt < 2; nt++) {
                uint32_t off = bOff0 + (uint32_t)nt * 16 * 128 + kk * 32;
                ldsm_x4(b[nt][0], b[nt][1], b[nt][2], b[nt][3],
                        stB + (off ^ bMask));
            }
#pragma unroll
            for (int mt = 0; mt < 4; mt++)
#pragma unroll
                for (int nt = 0; nt < 2; nt++) {
                    mma16816(acc[mt][2 * nt],     a[mt], b[nt][0], b[nt][1]);
                    mma16816(acc[mt][2 * nt + 1], a[mt], b[nt][2], b[nt][3]);
                }
        }
    }

    // Epilogue: direct stores; each 4-lane group writes a full 32B sector.
    const int b2 = nBase / SEQ;
    const int s0 = nBase % SEQ;
    const int mW = mBase + wm * 64;
    const int nW = s0 + wn * 32;
    const int rl = lane >> 2;
    const int cl = (lane & 3) * 2;
#pragma unroll
    for (int mt = 0; mt < 4; mt++) {
#pragma unroll
        for (int j = 0; j < 4; j++) {
            size_t base = ((size_t)b2 * MDIM + mW + mt * 16 + rl) * SEQ + nW + j * 8 + cl;
            *reinterpret_cast<float2*>(&out[base]) =
                make_float2(acc[mt][j][0], acc[mt][j][1]);
            *reinterpret_cast<float2*>(&out[base + 8 * SEQ]) =
                make_float2(acc[mt][j][2], acc[mt][j][3]);
        }
    }
}

// ---------------------------------------------------------------------------
// Launch
// ---------------------------------------------------------------------------
extern "C" void kernel_launch(void* const* d_in, const int* in_sizes, int n_in,
                              void* d_out, int out_size) {
    const float* x    = (const float*)d_in[0];   // [B, S, K]
    const float* w    = (const float*)d_in[1];   // [M, K]
    const int*   mask = (const int*)d_in[2];     // [M, K] bool -> int32
    float* out = (float*)d_out;                  // [B, M, S]

    convert_all<<<10240, 256>>>(x, w, mask);

    cudaFuncSetAttribute(gemm_hmma,
                         cudaFuncAttributeMaxDynamicSharedMemorySize, SMEM_TOTAL);
    dim3 grid(MDIM / BM, NDIM / BN);   // (32, 128): m fastest -> W stays in L2
    gemm_hmma<<<grid, GTHREADS, SMEM_TOTAL>>>(out);
}